// round 12
// baseline (speedup 1.0000x reference)
#include <cuda_runtime.h>

#define N_MAX 4096
#define D 1024
#define THR 0.25f
#define ROUNDS 4
#define W_SLOTS 512          // rows built per grid-wide pass
#define LANE_K 8             // per-lane sorted candidates kept (certified depth ~110-130)
#define T_FIN 6              // per-lane candidates in finish-resolver windows
#define FULLMASK 0xFFFFFFFFu

// ---------------- device state (static scratch; no runtime allocation) ----------------
__device__ float g_emb[N_MAX * D];
__device__ float g_ec[N_MAX * D];
__device__ float g_sim[(size_t)N_MAX * N_MAX + 128];                   // +pad for chunked tail
__device__ unsigned long long g_list6[(size_t)W_SLOTS * 32 * LANE_K];  // raw per-lane top-8
__device__ unsigned long long g_listB[W_SLOTS];                        // eviction bound per slot
__device__ unsigned int g_consumed[N_MAX / 32];
__device__ int g_idx[N_MAX];
__device__ int g_partner[N_MAX];
__device__ unsigned char g_alive[N_MAX];
__device__ int g_m;
__device__ int g_done;
__device__ int g_frontier;
__device__ int g_merges;
__device__ int g_ticket;

__device__ __forceinline__ unsigned long long warpmax_u64(unsigned long long v) {
#pragma unroll
    for (int off = 16; off > 0; off >>= 1) {
        unsigned long long o = __shfl_xor_sync(FULLMASK, v, off);
        if (o > v) v = o;
    }
    return v;
}

// ---------------- chunked pipelined row scan -> per-lane sorted top-T + eviction bound ----
template <int T>
__device__ __forceinline__ void proc4(float4 v, int cb, int r, int m,
                                      const unsigned int* cons,
                                      unsigned long long* loc,
                                      unsigned long long& eb) {
#pragma unroll
    for (int j = 0; j < 4; ++j) {
        float f = (j == 0) ? v.x : (j == 1) ? v.y : (j == 2) ? v.z : v.w;
        int b = cb + j;
        bool ok = (b > r) && (b < m) && !((cons[b >> 5] >> (b & 31)) & 1u);
        if (ok) {
            unsigned long long key =
                ((unsigned long long)__float_as_uint(f) << 32) |
                (unsigned int)(0xFFFFFFFFu - (unsigned)b);
            if (key > loc[T - 1]) {
                if (loc[T - 1] > eb) eb = loc[T - 1];
                loc[T - 1] = key;
#pragma unroll
                for (int t = T - 1; t > 0; --t)
                    if (loc[t] > loc[t - 1]) {
                        unsigned long long tmp = loc[t];
                        loc[t] = loc[t - 1];
                        loc[t - 1] = tmp;
                    }
            } else if (key > eb) {
                eb = key;
            }
        }
    }
}

template <int T>
__device__ __forceinline__ void scan_rowT(const float* __restrict__ row, int r, int m,
                                          const unsigned int* cons, int lane,
                                          unsigned long long* loc,
                                          unsigned long long& eb) {
    const int CH = 128;
    int base0 = (r + 1) & ~(CH - 1);
    int nch = (m - base0 + CH - 1) / CH;
    int off = base0 + lane * 4;
    float4 z = make_float4(0.f, 0.f, 0.f, 0.f);
    float4 c0 = (0 < nch) ? *(const float4*)(row + off) : z;
    float4 c1 = (1 < nch) ? *(const float4*)(row + off + CH) : z;
    for (int k = 0; k < nch; k += 2) {
        float4 n0 = (k + 2 < nch) ? *(const float4*)(row + off + (k + 2) * CH) : z;
        float4 n1 = (k + 3 < nch) ? *(const float4*)(row + off + (k + 3) * CH) : z;
        proc4<T>(c0, off + k * CH, r, m, cons, loc, eb);
        proc4<T>(c1, off + (k + 1) * CH, r, m, cons, loc, eb);
        c0 = n0;
        c1 = n1;
    }
}

// ---------------- init ----------------
__global__ void k_init(const float* __restrict__ in) {
    int i = blockIdx.x * blockDim.x + threadIdx.x;
    int stride = gridDim.x * blockDim.x;
    for (int t = i; t < N_MAX * D; t += stride) g_emb[t] = in[t];
    if (i < N_MAX) g_alive[i] = 1;
    if (i == 0) g_done = 0;
}

// ---------------- compact alive indices + per-round state reset ----------------
__global__ void k_compact() {  // <<<1,1024>>>
    int tid = threadIdx.x;
#pragma unroll
    for (int q = 0; q < 4; ++q) g_partner[tid * 4 + q] = -1;
    if (g_done) return;
    if (tid < N_MAX / 32) g_consumed[tid] = 0u;
    if (tid == 0) { g_frontier = 0; g_merges = 0; g_ticket = 0; }

    __shared__ int wsum[32];
    int base = tid * 4;
    int f0 = g_alive[base + 0];
    int f1 = g_alive[base + 1];
    int f2 = g_alive[base + 2];
    int f3 = g_alive[base + 3];
    int cnt = f0 + f1 + f2 + f3;
    int lane = tid & 31, wid = tid >> 5;
    int inc = cnt;
#pragma unroll
    for (int off = 1; off < 32; off <<= 1) {
        int u = __shfl_up_sync(FULLMASK, inc, off);
        if (lane >= off) inc += u;
    }
    if (lane == 31) wsum[wid] = inc;
    __syncthreads();
    if (wid == 0) {
        int v = wsum[lane];
#pragma unroll
        for (int off = 1; off < 32; off <<= 1) {
            int u = __shfl_up_sync(FULLMASK, v, off);
            if (lane >= off) v += u;
        }
        wsum[lane] = v;
    }
    __syncthreads();
    int ex = inc - cnt + (wid ? wsum[wid - 1] : 0);
    if (f0) g_idx[ex++] = base + 0;
    if (f1) g_idx[ex++] = base + 1;
    if (f2) g_idx[ex++] = base + 2;
    if (f3) g_idx[ex++] = base + 3;
    if (tid == 0) g_m = wsum[31];
}

// ---------------- gather compacted rows (zero-pad to N_MAX) ----------------
__global__ void k_gather() {  // <<<N_MAX, 256>>>
    if (g_done) return;
    int row = blockIdx.x;
    int m = g_m;
    float4* d = (float4*)(g_ec + (size_t)row * D);
    if (row < m) {
        const float4* s = (const float4*)(g_emb + (size_t)g_idx[row] * D);
        d[threadIdx.x] = s[threadIdx.x];
    } else {
        d[threadIdx.x] = make_float4(0.f, 0.f, 0.f, 0.f);
    }
}

// ---------------- fp32 SGEMM: sim[a][b] = dot(ec[a],ec[b])/D, upper-triangle tiles ----------------
__global__ void __launch_bounds__(256) k_gemm() {  // grid (32,32), 256 thr
    if (g_done) return;
    int m = g_m;
    int by = blockIdx.y;
    int bx = blockIdx.x;
    if (bx < by) return;
    if (by * 128 >= m || bx * 128 >= m) return;

    __shared__ __align__(16) float As[16][132];
    __shared__ __align__(16) float Bs[16][132];
    int tid = threadIdx.x;
    int lr = tid >> 2;
    int lq = tid & 3;
    int ty = tid >> 4;
    int tx = tid & 15;

    const float* Abase = g_ec + (size_t)(by * 128) * D;
    const float* Bbase = g_ec + (size_t)(bx * 128) * D;

    float acc[8][8] = {};

    for (int k0 = 0; k0 < D; k0 += 16) {
        float4 av0 = *(const float4*)(Abase + (size_t)lr * D + k0 + lq * 4);
        float4 av1 = *(const float4*)(Abase + (size_t)(lr + 64) * D + k0 + lq * 4);
        float4 bv0 = *(const float4*)(Bbase + (size_t)lr * D + k0 + lq * 4);
        float4 bv1 = *(const float4*)(Bbase + (size_t)(lr + 64) * D + k0 + lq * 4);
        __syncthreads();
        As[lq * 4 + 0][lr] = av0.x; As[lq * 4 + 1][lr] = av0.y;
        As[lq * 4 + 2][lr] = av0.z; As[lq * 4 + 3][lr] = av0.w;
        As[lq * 4 + 0][lr + 64] = av1.x; As[lq * 4 + 1][lr + 64] = av1.y;
        As[lq * 4 + 2][lr + 64] = av1.z; As[lq * 4 + 3][lr + 64] = av1.w;
        Bs[lq * 4 + 0][lr] = bv0.x; Bs[lq * 4 + 1][lr] = bv0.y;
        Bs[lq * 4 + 2][lr] = bv0.z; Bs[lq * 4 + 3][lr] = bv0.w;
        Bs[lq * 4 + 0][lr + 64] = bv1.x; Bs[lq * 4 + 1][lr + 64] = bv1.y;
        Bs[lq * 4 + 2][lr + 64] = bv1.z; Bs[lq * 4 + 3][lr + 64] = bv1.w;
        __syncthreads();
#pragma unroll
        for (int kk = 0; kk < 16; ++kk) {
            float4 a0 = *(const float4*)&As[kk][ty * 8];
            float4 a1 = *(const float4*)&As[kk][ty * 8 + 4];
            float4 b0 = *(const float4*)&Bs[kk][tx * 8];
            float4 b1 = *(const float4*)&Bs[kk][tx * 8 + 4];
            float ra[8] = {a0.x, a0.y, a0.z, a0.w, a1.x, a1.y, a1.z, a1.w};
            float rb[8] = {b0.x, b0.y, b0.z, b0.w, b1.x, b1.y, b1.z, b1.w};
#pragma unroll
            for (int i = 0; i < 8; ++i)
#pragma unroll
                for (int j = 0; j < 8; ++j) acc[i][j] += ra[i] * rb[j];
        }
    }

    const float s = 1.0f / (float)D;
#pragma unroll
    for (int i = 0; i < 8; ++i) {
        int a = by * 128 + ty * 8 + i;
        float* out = g_sim + (size_t)a * N_MAX + bx * 128 + tx * 8;
#pragma unroll
        for (int j = 0; j < 8; ++j) out[j] = acc[i][j] * s;
    }
}

// ========================= grid-wide pass machinery =========================

// Build: scan row, store raw per-lane top-8 (sorted desc) + eviction bound. No extraction.
__device__ void build8(int r, int m, int slot, const unsigned int* cons) {
    int lane = threadIdx.x & 31;
    if (r >= m) return;
    bool dead = (cons[r >> 5] >> (r & 31)) & 1u;
    unsigned long long loc[LANE_K];
#pragma unroll
    for (int t = 0; t < LANE_K; ++t) loc[t] = 0ULL;
    unsigned long long eb = 0ULL;
    if (!dead) scan_rowT<LANE_K>(g_sim + (size_t)r * N_MAX, r, m, cons, lane, loc, eb);

    unsigned long long* dst = g_list6 + ((size_t)slot * 32 + lane) * LANE_K;
    *(ulonglong2*)(dst + 0) = make_ulonglong2(loc[0], loc[1]);
    *(ulonglong2*)(dst + 2) = make_ulonglong2(loc[2], loc[3]);
    *(ulonglong2*)(dst + 4) = make_ulonglong2(loc[4], loc[5]);
    *(ulonglong2*)(dst + 6) = make_ulonglong2(loc[6], loc[7]);
    unsigned long long B = warpmax_u64(eb);
    if (lane == 0) g_listB[slot] = B;
}

__device__ __forceinline__ void load_slot8(int s, int n, int lane,
                                           ulonglong2& q0, ulonglong2& q1,
                                           ulonglong2& q2, ulonglong2& q3,
                                           unsigned long long& B) {
    if (s < n) {
        const unsigned long long* src = g_list6 + ((size_t)s * 32 + lane) * LANE_K;
        q0 = *(const ulonglong2*)(src + 0);
        q1 = *(const ulonglong2*)(src + 2);
        q2 = *(const ulonglong2*)(src + 4);
        q3 = *(const ulonglong2*)(src + 6);
        B = g_listB[s];
    } else {
        q0 = q1 = q2 = q3 = make_ulonglong2(0ULL, 0ULL);
        B = 0ULL;
    }
}

__device__ __forceinline__ bool row8(int a, int lane, unsigned int* cons,
                                     ulonglong2 q0, ulonglong2 q1,
                                     ulonglong2 q2, ulonglong2 q3,
                                     unsigned long long B, int& merges, int& stop) {
    bool ca = (cons[a >> 5] >> (a & 31)) & 1u;  // lane-uniform
    int partner = -1;
    if (!ca) {
        unsigned long long cand = 0ULL;
#pragma unroll
        for (int q = 0; q < 8; ++q) {
            unsigned long long k =
                (q == 0) ? q0.x : (q == 1) ? q0.y : (q == 2) ? q1.x : (q == 3) ? q1.y
                : (q == 4) ? q2.x : (q == 5) ? q2.y : (q == 6) ? q3.x : q3.y;
            if (cand == 0ULL && k != 0ULL) {
                int b = (int)(0xFFFFFFFFu - (unsigned int)(k & 0xFFFFFFFFull));
                if (!((cons[b >> 5] >> (b & 31)) & 1u)) cand = k;
            }
        }
        unsigned long long best = warpmax_u64(cand);
        if (best > B) {
            float v = __uint_as_float((unsigned int)(best >> 32));
            if (v >= THR)
                partner = (int)(0xFFFFFFFFu - (unsigned int)(best & 0xFFFFFFFFull));
        } else if (B != 0ULL) {
            stop = a;
            return false;
        }
    }
    if (partner >= 0) {
        ++merges;
        if (lane == 0) cons[partner >> 5] |= (1u << (partner & 31));
    }
    if (lane == 0) g_partner[a] = partner;
    __syncwarp();
    return true;
}

// Single-warp frontier sweep, 2-deep register pipeline.
__device__ void sweep_warp(int m, int F, unsigned int* cons) {
    int lane = threadIdx.x;  // warp 0 of last block
    int Wend = (F + W_SLOTS < m) ? (F + W_SLOTS) : m;
    int n = Wend - F;

    ulonglong2 a0, a1, a2, a3, b0, b1, b2, b3;
    unsigned long long BA, BB;
    load_slot8(0, n, lane, a0, a1, a2, a3, BA);
    load_slot8(1, n, lane, b0, b1, b2, b3, BB);

    int merges = 0, stop = -1;
    int s = 0;
    while (s < n && stop < 0) {
        if (!row8(F + s, lane, cons, a0, a1, a2, a3, BA, merges, stop)) break;
        load_slot8(s + 2, n, lane, a0, a1, a2, a3, BA);
        if (++s >= n) break;
        if (!row8(F + s, lane, cons, b0, b1, b2, b3, BB, merges, stop)) break;
        load_slot8(s + 2, n, lane, b0, b1, b2, b3, BB);
        ++s;
    }

    int newF = (stop >= 0) ? stop : Wend;
    for (int w = lane; w < N_MAX / 32; w += 32) g_consumed[w] = cons[w];
    if (lane == 0) {
        g_frontier = newF;
        g_merges += merges;
        if (newF == m) {
            int tm = g_merges;
            if (tm == 0 || (m - tm) <= 1) g_done = 1;
        }
    }
}

__global__ void __launch_bounds__(256) k_pass() {  // <<<W_SLOTS/8, 256>>>
    int m = *(volatile int*)&g_m;
    int F = *(volatile int*)&g_frontier;
    if (*(volatile int*)&g_done || F >= m) return;

    __shared__ unsigned int s_cons[N_MAX / 32];
    __shared__ int s_last;
    int tid = threadIdx.x;
    if (tid < N_MAX / 32) s_cons[tid] = g_consumed[tid];
    __syncthreads();

    int warp = tid >> 5;
    int slot = blockIdx.x * 8 + warp;
    build8(F + slot, m, slot, s_cons);

    __threadfence();
    __syncthreads();
    if (tid == 0) s_last = (atomicAdd(&g_ticket, 1) == (int)gridDim.x - 1);
    __syncthreads();
    if (!s_last) return;

    __threadfence();
    if (warp == 0) sweep_warp(m, F, s_cons);
    __syncthreads();
    if (tid == 0) g_ticket = 0;
}

// ---------------- finish: windowed certified resolver for leftovers (exact) ----------------
__global__ void __launch_bounds__(1024, 1) k_finish() {  // <<<1,1024>>>
    int m = g_m;
    if (g_done || g_frontier >= m) {
        // still must finalize done flag if frontier == m (k_pass sweep already did)
        return;
    }

    __shared__ unsigned int cons[N_MAX / 32];
    __shared__ unsigned long long keys[32][T_FIN][32];  // [row][t][lane]
    __shared__ unsigned long long sB[32];
    __shared__ int sF, sM;

    int tid = threadIdx.x, lane = tid & 31, wid = tid >> 5;
    if (tid < N_MAX / 32) cons[tid] = g_consumed[tid];
    if (tid == 0) { sF = g_frontier; sM = 0; }
    __syncthreads();

    int F = sF;
    while (F < m) {
        // build: warp wid -> row F+wid
        {
            int r = F + wid;
            unsigned long long loc[T_FIN];
#pragma unroll
            for (int t = 0; t < T_FIN; ++t) loc[t] = 0ULL;
            unsigned long long eb = 0ULL;
            bool dead = (r >= m) || ((cons[r >> 5] >> (r & 31)) & 1u);
            if (!dead)
                scan_rowT<T_FIN>(g_sim + (size_t)r * N_MAX, r, m, cons, lane, loc, eb);
#pragma unroll
            for (int t = 0; t < T_FIN; ++t) keys[wid][t][lane] = loc[t];
            unsigned long long B = warpmax_u64(eb);
            if (lane == 0) sB[wid] = B;
        }
        __syncthreads();

        // sweep: warp 0
        if (wid == 0) {
            volatile unsigned int* vc = cons;
            int Wend = (F + 32 < m) ? (F + 32) : m;
            int stop = -1;
            for (int a = F; a < Wend; ++a) {
                int s = a - F;
                bool ca = (vc[a >> 5] >> (a & 31)) & 1u;
                int partner = -1;
                if (!ca) {
                    unsigned long long cand = 0ULL;
#pragma unroll
                    for (int t = 0; t < T_FIN; ++t) {
                        unsigned long long k = keys[s][t][lane];
                        if (cand == 0ULL && k != 0ULL) {
                            int b = (int)(0xFFFFFFFFu - (unsigned int)(k & 0xFFFFFFFFull));
                            if (!((vc[b >> 5] >> (b & 31)) & 1u)) cand = k;
                        }
                    }
                    unsigned long long best = warpmax_u64(cand);
                    unsigned long long Bs = sB[s];
                    if (best > Bs) {
                        float v = __uint_as_float((unsigned int)(best >> 32));
                        if (v >= THR)
                            partner = (int)(0xFFFFFFFFu - (unsigned int)(best & 0xFFFFFFFFull));
                    } else if (Bs != 0ULL) {
                        stop = a;
                    }
                }
                if (stop >= 0) break;
                if (partner >= 0) {
                    if (lane == 0) {
                        vc[partner >> 5] |= (1u << (partner & 31));
                        ++sM;
                    }
                }
                if (lane == 0) g_partner[a] = partner;
                __syncwarp();
            }
            if (lane == 0) sF = (stop >= 0) ? stop : Wend;
        }
        __syncthreads();
        F = sF;
    }

    if (tid < N_MAX / 32) g_consumed[tid] = cons[tid];
    if (tid == 0) {
        g_frontier = m;
        g_merges += sM;
        int tm = g_merges;
        if (tm == 0 || (m - tm) <= 1) g_done = 1;
    }
}

// ---------------- apply merges: fuse initiator, zero+kill partner ----------------
__global__ void k_apply() {  // <<<N_MAX, 256>>>
    int a = blockIdx.x;
    int p = g_partner[a];
    if (p < 0) return;
    int gi = g_idx[a];
    int gj = g_idx[p];
    float4* vi = (float4*)(g_emb + (size_t)gi * D);
    float4* vj = (float4*)(g_emb + (size_t)gj * D);
    int t = threadIdx.x;
    float4 x = vi[t];
    float4 y = vj[t];
    x.x = fminf(x.x + y.x, 1.0f);
    x.y = fminf(x.y + y.y, 1.0f);
    x.z = fminf(x.z + y.z, 1.0f);
    x.w = fminf(x.w + y.w, 1.0f);
    vi[t] = x;
    vj[t] = make_float4(0.f, 0.f, 0.f, 0.f);
    if (t == 0) g_alive[gj] = 0;
}

// ---------------- write output: emb then alive (as float) ----------------
__global__ void k_output(float* __restrict__ out, int out_size) {
    int i = blockIdx.x * blockDim.x + threadIdx.x;
    int stride = gridDim.x * blockDim.x;
    for (int t = i; t < N_MAX * D; t += stride)
        if (t < out_size) out[t] = g_emb[t];
    for (int r = i; r < N_MAX; r += stride) {
        int o = N_MAX * D + r;
        if (o < out_size) out[o] = g_alive[r] ? 1.0f : 0.0f;
    }
}

extern "C" void kernel_launch(void* const* d_in, const int* in_sizes, int n_in,
                              void* d_out, int out_size) {
    const float* in = (const float*)d_in[0];
    static const int pass_budget[ROUNDS] = {9, 20, 10, 7};
    k_init<<<4096, 256>>>(in);
    for (int r = 0; r < ROUNDS; ++r) {
        k_compact<<<1, 1024>>>();
        k_gather<<<N_MAX, 256>>>();
        dim3 grid(32, 32);
        k_gemm<<<grid, 256>>>();
        for (int p = 0; p < pass_budget[r]; ++p)
            k_pass<<<W_SLOTS / 8, 256>>>();
        k_finish<<<1, 1024>>>();
        k_apply<<<N_MAX, 256>>>();
    }
    k_output<<<4096, 256>>>((float*)d_out, out_size);
}

// round 13
// speedup vs baseline: 1.3634x; 1.3634x over previous
#include <cuda_runtime.h>

#define N_MAX 4096
#define D 1024
#define THR 0.25f
#define ROUNDS 4
#define W_SLOTS 512          // rows built per pass
#define T_LANE 6             // per-lane sorted candidates in build
#define FULLMASK 0xFFFFFFFFu

// ---------------- device state (static scratch; no runtime allocation) ----------------
__device__ float g_emb[N_MAX * D];
__device__ float g_ec[N_MAX * D];
__device__ float g_sim[(size_t)N_MAX * N_MAX + 128];   // +128 pad for chunked tail reads
__device__ unsigned long long g_fresh[W_SLOTS * 32];   // per-slot sorted top-L keys
__device__ int g_freshmeta[W_SLOTS];                   // L | complete<<16
__device__ unsigned int g_consumed[N_MAX / 32];
__device__ int g_idx[N_MAX];
__device__ int g_partner[N_MAX];
__device__ unsigned char g_alive[N_MAX];
__device__ int g_m;
__device__ int g_done;
__device__ int g_frontier;
__device__ int g_merges;
__device__ int g_ticket;

__device__ __forceinline__ unsigned long long warpmax_u64(unsigned long long v) {
#pragma unroll
    for (int off = 16; off > 0; off >>= 1) {
        unsigned long long o = __shfl_xor_sync(FULLMASK, v, off);
        if (o > v) v = o;
    }
    return v;
}

// ---------------- chunked pipelined row scan -> per-lane sorted top-6 + eviction bound ----
__device__ __forceinline__ void proc4(float4 v, int cb, int r, int m,
                                      const unsigned int* cons,
                                      unsigned long long* loc,
                                      unsigned long long& eb) {
#pragma unroll
    for (int j = 0; j < 4; ++j) {
        float f = (j == 0) ? v.x : (j == 1) ? v.y : (j == 2) ? v.z : v.w;
        int b = cb + j;
        bool ok = (b > r) && (b < m) && !((cons[b >> 5] >> (b & 31)) & 1u);
        if (ok) {
            unsigned long long key =
                ((unsigned long long)__float_as_uint(f) << 32) |
                (unsigned int)(0xFFFFFFFFu - (unsigned)b);
            if (key > loc[T_LANE - 1]) {
                if (loc[T_LANE - 1] > eb) eb = loc[T_LANE - 1];
                loc[T_LANE - 1] = key;
#pragma unroll
                for (int t = T_LANE - 1; t > 0; --t)
                    if (loc[t] > loc[t - 1]) {
                        unsigned long long tmp = loc[t];
                        loc[t] = loc[t - 1];
                        loc[t - 1] = tmp;
                    }
            } else if (key > eb) {
                eb = key;
            }
        }
    }
}

__device__ __forceinline__ void scan_row6(const float* __restrict__ row, int r, int m,
                                          const unsigned int* cons, int lane,
                                          unsigned long long* loc,
                                          unsigned long long& eb) {
    const int CH = 128;  // elements per chunk (32 lanes x float4)
    int base0 = (r + 1) & ~(CH - 1);
    int nch = (m - base0 + CH - 1) / CH;
    int off = base0 + lane * 4;
    float4 z = make_float4(0.f, 0.f, 0.f, 0.f);
    float4 c0 = (0 < nch) ? *(const float4*)(row + off) : z;
    float4 c1 = (1 < nch) ? *(const float4*)(row + off + CH) : z;
    for (int k = 0; k < nch; k += 2) {
        float4 n0 = (k + 2 < nch) ? *(const float4*)(row + off + (k + 2) * CH) : z;
        float4 n1 = (k + 3 < nch) ? *(const float4*)(row + off + (k + 3) * CH) : z;
        proc4(c0, off + k * CH, r, m, cons, loc, eb);
        proc4(c1, off + (k + 1) * CH, r, m, cons, loc, eb);
        c0 = n0;
        c1 = n1;
    }
}

// ---------------- init ----------------
__global__ void k_init(const float* __restrict__ in) {
    int i = blockIdx.x * blockDim.x + threadIdx.x;
    int stride = gridDim.x * blockDim.x;
    for (int t = i; t < N_MAX * D; t += stride) g_emb[t] = in[t];
    if (i < N_MAX) g_alive[i] = 1;
    if (i == 0) g_done = 0;
}

// ---------------- compact alive indices + per-round state reset ----------------
__global__ void k_compact() {  // <<<1,1024>>>
    int tid = threadIdx.x;
    if (g_done) {
#pragma unroll
        for (int q = 0; q < 4; ++q) g_partner[tid * 4 + q] = -1;
        return;
    }
#pragma unroll
    for (int q = 0; q < 4; ++q) g_partner[tid * 4 + q] = -1;
    if (tid < N_MAX / 32) g_consumed[tid] = 0u;
    if (tid == 0) { g_frontier = 0; g_merges = 0; g_ticket = 0; }

    __shared__ int wsum[32];
    int base = tid * 4;
    int f0 = g_alive[base + 0];
    int f1 = g_alive[base + 1];
    int f2 = g_alive[base + 2];
    int f3 = g_alive[base + 3];
    int cnt = f0 + f1 + f2 + f3;
    int lane = tid & 31, wid = tid >> 5;
    int inc = cnt;
#pragma unroll
    for (int off = 1; off < 32; off <<= 1) {
        int u = __shfl_up_sync(FULLMASK, inc, off);
        if (lane >= off) inc += u;
    }
    if (lane == 31) wsum[wid] = inc;
    __syncthreads();
    if (wid == 0) {
        int v = wsum[lane];
#pragma unroll
        for (int off = 1; off < 32; off <<= 1) {
            int u = __shfl_up_sync(FULLMASK, v, off);
            if (lane >= off) v += u;
        }
        wsum[lane] = v;
    }
    __syncthreads();
    int ex = inc - cnt + (wid ? wsum[wid - 1] : 0);
    if (f0) g_idx[ex++] = base + 0;
    if (f1) g_idx[ex++] = base + 1;
    if (f2) g_idx[ex++] = base + 2;
    if (f3) g_idx[ex++] = base + 3;
    if (tid == 0) g_m = wsum[31];
}

// ---------------- gather compacted rows (zero-pad to N_MAX) ----------------
__global__ void k_gather() {  // <<<N_MAX, 256>>>
    if (g_done) return;
    int row = blockIdx.x;
    int m = g_m;
    float4* d = (float4*)(g_ec + (size_t)row * D);
    if (row < m) {
        const float4* s = (const float4*)(g_emb + (size_t)g_idx[row] * D);
        d[threadIdx.x] = s[threadIdx.x];
    } else {
        d[threadIdx.x] = make_float4(0.f, 0.f, 0.f, 0.f);
    }
}

// ---------------- fp32 SGEMM: sim[a][b] = dot(ec[a],ec[b])/D, upper-triangle tiles ----------------
__global__ void __launch_bounds__(256) k_gemm() {  // grid (32,32), 256 thr
    if (g_done) return;
    int m = g_m;
    int by = blockIdx.y;
    int bx = blockIdx.x;
    if (bx < by) return;
    if (by * 128 >= m || bx * 128 >= m) return;

    __shared__ __align__(16) float As[16][132];
    __shared__ __align__(16) float Bs[16][132];
    int tid = threadIdx.x;
    int lr = tid >> 2;
    int lq = tid & 3;
    int ty = tid >> 4;
    int tx = tid & 15;

    const float* Abase = g_ec + (size_t)(by * 128) * D;
    const float* Bbase = g_ec + (size_t)(bx * 128) * D;

    float acc[8][8] = {};

    for (int k0 = 0; k0 < D; k0 += 16) {
        float4 av0 = *(const float4*)(Abase + (size_t)lr * D + k0 + lq * 4);
        float4 av1 = *(const float4*)(Abase + (size_t)(lr + 64) * D + k0 + lq * 4);
        float4 bv0 = *(const float4*)(Bbase + (size_t)lr * D + k0 + lq * 4);
        float4 bv1 = *(const float4*)(Bbase + (size_t)(lr + 64) * D + k0 + lq * 4);
        __syncthreads();
        As[lq * 4 + 0][lr] = av0.x; As[lq * 4 + 1][lr] = av0.y;
        As[lq * 4 + 2][lr] = av0.z; As[lq * 4 + 3][lr] = av0.w;
        As[lq * 4 + 0][lr + 64] = av1.x; As[lq * 4 + 1][lr + 64] = av1.y;
        As[lq * 4 + 2][lr + 64] = av1.z; As[lq * 4 + 3][lr + 64] = av1.w;
        Bs[lq * 4 + 0][lr] = bv0.x; Bs[lq * 4 + 1][lr] = bv0.y;
        Bs[lq * 4 + 2][lr] = bv0.z; Bs[lq * 4 + 3][lr] = bv0.w;
        Bs[lq * 4 + 0][lr + 64] = bv1.x; Bs[lq * 4 + 1][lr + 64] = bv1.y;
        Bs[lq * 4 + 2][lr + 64] = bv1.z; Bs[lq * 4 + 3][lr + 64] = bv1.w;
        __syncthreads();
#pragma unroll
        for (int kk = 0; kk < 16; ++kk) {
            float4 a0 = *(const float4*)&As[kk][ty * 8];
            float4 a1 = *(const float4*)&As[kk][ty * 8 + 4];
            float4 b0 = *(const float4*)&Bs[kk][tx * 8];
            float4 b1 = *(const float4*)&Bs[kk][tx * 8 + 4];
            float ra[8] = {a0.x, a0.y, a0.z, a0.w, a1.x, a1.y, a1.z, a1.w};
            float rb[8] = {b0.x, b0.y, b0.z, b0.w, b1.x, b1.y, b1.z, b1.w};
#pragma unroll
            for (int i = 0; i < 8; ++i)
#pragma unroll
                for (int j = 0; j < 8; ++j) acc[i][j] += ra[i] * rb[j];
        }
    }

    const float s = 1.0f / (float)D;
#pragma unroll
    for (int i = 0; i < 8; ++i) {
        int a = by * 128 + ty * 8 + i;
        float* out = g_sim + (size_t)a * N_MAX + bx * 128 + tx * 8;
#pragma unroll
        for (int j = 0; j < 8; ++j) out[j] = acc[i][j] * s;
    }
}

// ---------------- per-pass fresh list build (pipelined scan + exact sorted top-L<=32) ----
__device__ void build_fresh(int r, int m, int slot, const unsigned int* cons) {
    int lane = threadIdx.x & 31;
    if (r >= m) return;  // slot never read by sweep
    bool dead = (cons[r >> 5] >> (r & 31)) & 1u;
    if (dead) {
        if (lane == 0) g_freshmeta[slot] = (1 << 16);  // L=0, complete
        return;
    }
    unsigned long long loc[T_LANE];
#pragma unroll
    for (int t = 0; t < T_LANE; ++t) loc[t] = 0ULL;
    unsigned long long eb = 0ULL;  // max evicted key
    scan_row6(g_sim + (size_t)r * N_MAX, r, m, cons, lane, loc, eb);

    unsigned long long B = warpmax_u64(eb);
    unsigned long long* dst = g_fresh + (size_t)slot * 32;
    int hp = 0, L = 0, complete = 0;
    for (int step = 0; step < 32; ++step) {
        unsigned long long hv = (hp < T_LANE) ? loc[hp] : 0ULL;
        unsigned long long h = warpmax_u64(hv);
        if (h == 0ULL) { if (B == 0ULL) complete = 1; break; }
        if (h < B) break;  // unknown evicted key could outrank h
        unsigned ball = __ballot_sync(FULLMASK, hv == h);
        if (lane == __ffs(ball) - 1) {
            dst[step] = h;
            hp++;
        }
        L++;
    }
    if (lane == 0) g_freshmeta[slot] = L | (complete << 16);
}

// ---------------- single-warp frontier sweep over fresh lists (2-deep prefetch) ----------
__device__ void sweep_warp(int m, int F, unsigned int* cons /*shared*/) {
    int lane = threadIdx.x;  // warp 0 only
    int Wend = (F + W_SLOTS < m) ? (F + W_SLOTS) : m;
    int n = Wend - F;

    unsigned long long kA = (n > 0 && lane < 32) ? g_fresh[0 * 32 + lane] : 0ULL;
    int mA = (n > 0) ? g_freshmeta[0] : 0;
    unsigned long long kB = (n > 1) ? g_fresh[1 * 32 + lane] : 0ULL;
    int mB = (n > 1) ? g_freshmeta[1] : 0;

    int merges = 0;
    int stop = -1;

    for (int a = F; a < Wend; ++a) {
        int slot = a - F;
        unsigned long long kC = (slot + 2 < n) ? g_fresh[(size_t)(slot + 2) * 32 + lane] : 0ULL;
        int mC = (slot + 2 < n) ? g_freshmeta[slot + 2] : 0;

        bool ca = (cons[a >> 5] >> (a & 31)) & 1u;  // lane-uniform
        int partner = -1;
        if (!ca) {
            int L = mA & 0xFFFF;
            int comp = mA >> 16;
            unsigned long long k = (lane < L) ? kA : 0ULL;
            int b = (int)((0xFFFFFFFFu - (unsigned int)(k & 0xFFFFFFFFull)) & (N_MAX - 1));
            bool avail = (k != 0ULL) && !((cons[b >> 5] >> (b & 31)) & 1u);
            unsigned ba = __ballot_sync(FULLMASK, avail);
            if (ba) {
                unsigned long long kf = __shfl_sync(FULLMASK, kA, __ffs(ba) - 1);
                float v = __uint_as_float((unsigned int)(kf >> 32));
                if (v >= THR)
                    partner = (int)(0xFFFFFFFFu - (unsigned int)(kf & 0xFFFFFFFFull));
            } else if (!comp) {
                stop = a;  // stale list, rebuild next pass
            }
        }
        if (stop >= 0) break;
        if (partner >= 0) {
            ++merges;
            if (lane == 0) cons[partner >> 5] |= (1u << (partner & 31));
        }
        if (lane == 0) g_partner[a] = partner;
        __syncwarp();
        kA = kB; mA = mB; kB = kC; mB = mC;
    }

    int newF = (stop >= 0) ? stop : Wend;
    for (int w = lane; w < N_MAX / 32; w += 32) g_consumed[w] = cons[w];
    if (lane == 0) {
        g_frontier = newF;
        g_merges += merges;
        if (newF == m) {
            int tm = g_merges;
            if (tm == 0 || (m - tm) <= 1) g_done = 1;
        }
    }
}

// ---------------- one pass: parallel fresh builds + (last block) sequential sweep ----------------
__global__ void __launch_bounds__(256) k_pass() {  // <<<W_SLOTS/8, 256>>>
    int m = *(volatile int*)&g_m;
    int F = *(volatile int*)&g_frontier;
    if (*(volatile int*)&g_done || F >= m) return;

    __shared__ unsigned int s_cons[N_MAX / 32];
    __shared__ int s_last;
    int tid = threadIdx.x;
    if (tid < N_MAX / 32) s_cons[tid] = g_consumed[tid];
    __syncthreads();

    int warp = tid >> 5;
    int slot = blockIdx.x * 8 + warp;
    build_fresh(F + slot, m, slot, s_cons);

    __threadfence();   // release this thread's list writes
    __syncthreads();
    if (tid == 0) s_last = (atomicAdd(&g_ticket, 1) == (int)gridDim.x - 1);
    __syncthreads();
    if (!s_last) return;

    __threadfence();   // acquire other blocks' list writes
    if (warp == 0) sweep_warp(m, F, s_cons);
    __syncthreads();
    if (tid == 0) g_ticket = 0;
}

// ---------------- exact finish net: block-rescan remaining rows (normally a no-op) ------------
__global__ void __launch_bounds__(1024, 1) k_finish() {  // <<<1,1024>>>
    int m = g_m;
    int F = g_frontier;
    if (g_done || F >= m) return;

    __shared__ unsigned int cons[N_MAX / 32];
    __shared__ unsigned long long partial[32];
    int tid = threadIdx.x, lane = tid & 31, wid = tid >> 5;
    if (tid < N_MAX / 32) cons[tid] = g_consumed[tid];
    __syncthreads();

    int merges = 0;  // maintained by thread 0 only
    for (int a = F; a < m; ++a) {
        bool ca = (cons[a >> 5] >> (a & 31)) & 1u;  // uniform
        unsigned long long best = 0ULL;
        if (!ca) {
            const float* row = g_sim + (size_t)a * N_MAX;
            for (int b = a + 1 + tid; b < m; b += 1024) {
                if (!((cons[b >> 5] >> (b & 31)) & 1u)) {
                    unsigned long long key =
                        ((unsigned long long)__float_as_uint(row[b]) << 32) |
                        (unsigned int)(0xFFFFFFFFu - (unsigned)b);
                    if (key > best) best = key;
                }
            }
        }
        best = warpmax_u64(best);
        if (lane == 0) partial[wid] = best;
        __syncthreads();
        if (wid == 0) {
            unsigned long long p = warpmax_u64(partial[lane]);
            if (lane == 0) {
                int partner = -1;
                if (!ca && p != 0ULL) {
                    float v = __uint_as_float((unsigned int)(p >> 32));
                    if (v >= THR)
                        partner = (int)(0xFFFFFFFFu - (unsigned int)(p & 0xFFFFFFFFull));
                }
                g_partner[a] = partner;
                if (partner >= 0) {
                    ++merges;
                    cons[partner >> 5] |= (1u << (partner & 31));
                }
            }
        }
        __syncthreads();
    }
    if (tid < N_MAX / 32) g_consumed[tid] = cons[tid];
    if (tid == 0) {
        g_frontier = m;
        g_merges += merges;
        int tm = g_merges;
        if (tm == 0 || (m - tm) <= 1) g_done = 1;
    }
}

// ---------------- apply merges: fuse initiator, zero+kill partner ----------------
__global__ void k_apply() {  // <<<N_MAX, 256>>>
    int a = blockIdx.x;
    int p = g_partner[a];
    if (p < 0) return;
    int gi = g_idx[a];
    int gj = g_idx[p];
    float4* vi = (float4*)(g_emb + (size_t)gi * D);
    float4* vj = (float4*)(g_emb + (size_t)gj * D);
    int t = threadIdx.x;
    float4 x = vi[t];
    float4 y = vj[t];
    x.x = fminf(x.x + y.x, 1.0f);
    x.y = fminf(x.y + y.y, 1.0f);
    x.z = fminf(x.z + y.z, 1.0f);
    x.w = fminf(x.w + y.w, 1.0f);
    vi[t] = x;
    vj[t] = make_float4(0.f, 0.f, 0.f, 0.f);
    if (t == 0) g_alive[gj] = 0;
}

// ---------------- write output: emb then alive (as float) ----------------
__global__ void k_output(float* __restrict__ out, int out_size) {
    int i = blockIdx.x * blockDim.x + threadIdx.x;
    int stride = gridDim.x * blockDim.x;
    for (int t = i; t < N_MAX * D; t += stride)
        if (t < out_size) out[t] = g_emb[t];
    for (int r = i; r < N_MAX; r += stride) {
        int o = N_MAX * D + r;
        if (o < out_size) out[o] = g_alive[r] ? 1.0f : 0.0f;
    }
}

extern "C" void kernel_launch(void* const* d_in, const int* in_sizes, int n_in,
                              void* d_out, int out_size) {
    const float* in = (const float*)d_in[0];
    static const int pass_budget[ROUNDS] = {12, 32, 20, 12};
    k_init<<<4096, 256>>>(in);
    for (int r = 0; r < ROUNDS; ++r) {
        k_compact<<<1, 1024>>>();
        k_gather<<<N_MAX, 256>>>();
        dim3 grid(32, 32);
        k_gemm<<<grid, 256>>>();
        for (int p = 0; p < pass_budget[r]; ++p)
            k_pass<<<W_SLOTS / 8, 256>>>();
        k_finish<<<1, 1024>>>();
        k_apply<<<N_MAX, 256>>>();
    }
    k_output<<<4096, 256>>>((float*)d_out, out_size);
}

// round 15
// speedup vs baseline: 1.6100x; 1.1809x over previous
#include <cuda_runtime.h>

#define N_MAX 4096
#define D 1024
#define THR 0.25f
#define ROUNDS 4
#define W_SLOTS 512          // rows built per pass
#define LISTN 64             // entries per fresh list
#define T_LANE 6             // per-lane sorted candidates in build
#define FULLMASK 0xFFFFFFFFu

// ---------------- device state (static scratch; no runtime allocation) ----------------
__device__ float g_emb[N_MAX * D];
__device__ float g_ec[N_MAX * D];
__device__ float g_sim[(size_t)N_MAX * N_MAX + 128];    // +128 pad for chunked tail reads
__device__ unsigned long long g_fresh[W_SLOTS * LISTN]; // per-slot sorted top-L keys
__device__ int g_freshmeta[W_SLOTS];                    // L | complete<<16
__device__ unsigned int g_consumed[N_MAX / 32];
__device__ int g_idx[N_MAX];
__device__ int g_partner[N_MAX];
__device__ unsigned char g_alive[N_MAX];
__device__ int g_m;
__device__ int g_done;
__device__ int g_frontier;
__device__ int g_merges;
__device__ int g_ticket;

__device__ __forceinline__ unsigned long long warpmax_u64(unsigned long long v) {
#pragma unroll
    for (int off = 16; off > 0; off >>= 1) {
        unsigned long long o = __shfl_xor_sync(FULLMASK, v, off);
        if (o > v) v = o;
    }
    return v;
}

// ---------------- chunked pipelined row scan -> per-lane sorted top-6 + eviction bound ----
__device__ __forceinline__ void proc4(float4 v, int cb, int r, int m,
                                      const unsigned int* cons,
                                      unsigned long long* loc,
                                      unsigned long long& eb) {
#pragma unroll
    for (int j = 0; j < 4; ++j) {
        float f = (j == 0) ? v.x : (j == 1) ? v.y : (j == 2) ? v.z : v.w;
        int b = cb + j;
        bool ok = (b > r) && (b < m) && !((cons[b >> 5] >> (b & 31)) & 1u);
        if (ok) {
            unsigned long long key =
                ((unsigned long long)__float_as_uint(f) << 32) |
                (unsigned int)(0xFFFFFFFFu - (unsigned)b);
            if (key > loc[T_LANE - 1]) {
                if (loc[T_LANE - 1] > eb) eb = loc[T_LANE - 1];
                loc[T_LANE - 1] = key;
#pragma unroll
                for (int t = T_LANE - 1; t > 0; --t)
                    if (loc[t] > loc[t - 1]) {
                        unsigned long long tmp = loc[t];
                        loc[t] = loc[t - 1];
                        loc[t - 1] = tmp;
                    }
            } else if (key > eb) {
                eb = key;
            }
        }
    }
}

__device__ __forceinline__ void scan_row6(const float* __restrict__ row, int r, int m,
                                          const unsigned int* cons, int lane,
                                          unsigned long long* loc,
                                          unsigned long long& eb) {
    const int CH = 128;  // elements per chunk (32 lanes x float4)
    int base0 = (r + 1) & ~(CH - 1);
    int nch = (m - base0 + CH - 1) / CH;
    int off = base0 + lane * 4;
    float4 z = make_float4(0.f, 0.f, 0.f, 0.f);
    float4 c0 = (0 < nch) ? *(const float4*)(row + off) : z;
    float4 c1 = (1 < nch) ? *(const float4*)(row + off + CH) : z;
    for (int k = 0; k < nch; k += 2) {
        float4 n0 = (k + 2 < nch) ? *(const float4*)(row + off + (k + 2) * CH) : z;
        float4 n1 = (k + 3 < nch) ? *(const float4*)(row + off + (k + 3) * CH) : z;
        proc4(c0, off + k * CH, r, m, cons, loc, eb);
        proc4(c1, off + (k + 1) * CH, r, m, cons, loc, eb);
        c0 = n0;
        c1 = n1;
    }
}

// ---------------- init ----------------
__global__ void k_init(const float* __restrict__ in) {
    int i = blockIdx.x * blockDim.x + threadIdx.x;
    int stride = gridDim.x * blockDim.x;
    for (int t = i; t < N_MAX * D; t += stride) g_emb[t] = in[t];
    if (i < N_MAX) g_alive[i] = 1;
    if (i == 0) g_done = 0;
}

// ---------------- compact alive indices + per-round state reset ----------------
__global__ void k_compact() {  // <<<1,1024>>>
    int tid = threadIdx.x;
    if (g_done) {
#pragma unroll
        for (int q = 0; q < 4; ++q) g_partner[tid * 4 + q] = -1;
        return;
    }
#pragma unroll
    for (int q = 0; q < 4; ++q) g_partner[tid * 4 + q] = -1;
    if (tid < N_MAX / 32) g_consumed[tid] = 0u;
    if (tid == 0) { g_frontier = 0; g_merges = 0; g_ticket = 0; }

    __shared__ int wsum[32];
    int base = tid * 4;
    int f0 = g_alive[base + 0];
    int f1 = g_alive[base + 1];
    int f2 = g_alive[base + 2];
    int f3 = g_alive[base + 3];
    int cnt = f0 + f1 + f2 + f3;
    int lane = tid & 31, wid = tid >> 5;
    int inc = cnt;
#pragma unroll
    for (int off = 1; off < 32; off <<= 1) {
        int u = __shfl_up_sync(FULLMASK, inc, off);
        if (lane >= off) inc += u;
    }
    if (lane == 31) wsum[wid] = inc;
    __syncthreads();
    if (wid == 0) {
        int v = wsum[lane];
#pragma unroll
        for (int off = 1; off < 32; off <<= 1) {
            int u = __shfl_up_sync(FULLMASK, v, off);
            if (lane >= off) v += u;
        }
        wsum[lane] = v;
    }
    __syncthreads();
    int ex = inc - cnt + (wid ? wsum[wid - 1] : 0);
    if (f0) g_idx[ex++] = base + 0;
    if (f1) g_idx[ex++] = base + 1;
    if (f2) g_idx[ex++] = base + 2;
    if (f3) g_idx[ex++] = base + 3;
    if (tid == 0) g_m = wsum[31];
}

// ---------------- gather compacted rows (zero-pad to N_MAX) ----------------
__global__ void k_gather() {  // <<<N_MAX, 256>>>
    if (g_done) return;
    int row = blockIdx.x;
    int m = g_m;
    float4* d = (float4*)(g_ec + (size_t)row * D);
    if (row < m) {
        const float4* s = (const float4*)(g_emb + (size_t)g_idx[row] * D);
        d[threadIdx.x] = s[threadIdx.x];
    } else {
        d[threadIdx.x] = make_float4(0.f, 0.f, 0.f, 0.f);
    }
}

// ---------------- fp32 SGEMM: sim[a][b] = dot(ec[a],ec[b])/D, upper-triangle tiles ----------------
__global__ void __launch_bounds__(256) k_gemm() {  // grid (32,32), 256 thr
    if (g_done) return;
    int m = g_m;
    int by = blockIdx.y;
    int bx = blockIdx.x;
    if (bx < by) return;
    if (by * 128 >= m || bx * 128 >= m) return;

    __shared__ __align__(16) float As[16][132];
    __shared__ __align__(16) float Bs[16][132];
    int tid = threadIdx.x;
    int lr = tid >> 2;
    int lq = tid & 3;
    int ty = tid >> 4;
    int tx = tid & 15;

    const float* Abase = g_ec + (size_t)(by * 128) * D;
    const float* Bbase = g_ec + (size_t)(bx * 128) * D;

    float acc[8][8] = {};

    for (int k0 = 0; k0 < D; k0 += 16) {
        float4 av0 = *(const float4*)(Abase + (size_t)lr * D + k0 + lq * 4);
        float4 av1 = *(const float4*)(Abase + (size_t)(lr + 64) * D + k0 + lq * 4);
        float4 bv0 = *(const float4*)(Bbase + (size_t)lr * D + k0 + lq * 4);
        float4 bv1 = *(const float4*)(Bbase + (size_t)(lr + 64) * D + k0 + lq * 4);
        __syncthreads();
        As[lq * 4 + 0][lr] = av0.x; As[lq * 4 + 1][lr] = av0.y;
        As[lq * 4 + 2][lr] = av0.z; As[lq * 4 + 3][lr] = av0.w;
        As[lq * 4 + 0][lr + 64] = av1.x; As[lq * 4 + 1][lr + 64] = av1.y;
        As[lq * 4 + 2][lr + 64] = av1.z; As[lq * 4 + 3][lr + 64] = av1.w;
        Bs[lq * 4 + 0][lr] = bv0.x; Bs[lq * 4 + 1][lr] = bv0.y;
        Bs[lq * 4 + 2][lr] = bv0.z; Bs[lq * 4 + 3][lr] = bv0.w;
        Bs[lq * 4 + 0][lr + 64] = bv1.x; Bs[lq * 4 + 1][lr + 64] = bv1.y;
        Bs[lq * 4 + 2][lr + 64] = bv1.z; Bs[lq * 4 + 3][lr + 64] = bv1.w;
        __syncthreads();
#pragma unroll
        for (int kk = 0; kk < 16; ++kk) {
            float4 a0 = *(const float4*)&As[kk][ty * 8];
            float4 a1 = *(const float4*)&As[kk][ty * 8 + 4];
            float4 b0 = *(const float4*)&Bs[kk][tx * 8];
            float4 b1 = *(const float4*)&Bs[kk][tx * 8 + 4];
            float ra[8] = {a0.x, a0.y, a0.z, a0.w, a1.x, a1.y, a1.z, a1.w};
            float rb[8] = {b0.x, b0.y, b0.z, b0.w, b1.x, b1.y, b1.z, b1.w};
#pragma unroll
            for (int i = 0; i < 8; ++i)
#pragma unroll
                for (int j = 0; j < 8; ++j) acc[i][j] += ra[i] * rb[j];
        }
    }

    const float s = 1.0f / (float)D;
#pragma unroll
    for (int i = 0; i < 8; ++i) {
        int a = by * 128 + ty * 8 + i;
        float* out = g_sim + (size_t)a * N_MAX + bx * 128 + tx * 8;
#pragma unroll
        for (int j = 0; j < 8; ++j) out[j] = acc[i][j] * s;
    }
}

// ---------------- per-pass fresh list build (pipelined scan + exact sorted top-L<=64) ----
__device__ void build_fresh(int r, int m, int slot, const unsigned int* cons) {
    int lane = threadIdx.x & 31;
    if (r >= m) return;  // slot never read by sweep
    bool dead = (cons[r >> 5] >> (r & 31)) & 1u;
    if (dead) {
        if (lane == 0) g_freshmeta[slot] = (1 << 16);  // L=0, complete
        return;
    }
    unsigned long long loc[T_LANE];
#pragma unroll
    for (int t = 0; t < T_LANE; ++t) loc[t] = 0ULL;
    unsigned long long eb = 0ULL;  // max evicted key
    scan_row6(g_sim + (size_t)r * N_MAX, r, m, cons, lane, loc, eb);

    unsigned long long B = warpmax_u64(eb);
    unsigned long long* dst = g_fresh + (size_t)slot * LISTN;
    int hp = 0, L = 0, complete = 0;
    for (int step = 0; step < LISTN; ++step) {
        unsigned long long hv = (hp < T_LANE) ? loc[hp] : 0ULL;
        unsigned long long h = warpmax_u64(hv);
        if (h == 0ULL) { if (B == 0ULL) complete = 1; break; }
        if (h < B) break;  // unknown evicted key could outrank h
        unsigned ball = __ballot_sync(FULLMASK, hv == h);
        if (lane == __ffs(ball) - 1) {
            dst[step] = h;
            hp++;
        }
        L++;
    }
    if (lane == 0) g_freshmeta[slot] = L | (complete << 16);
}

// ---------------- sweep helpers ----------------
__device__ __forceinline__ void load_slotp(int s, int n, int lane,
                                           ulonglong2& q, int& meta) {
    if (s < n) {
        q = *(const ulonglong2*)(g_fresh + (size_t)s * LISTN + lane * 2);
        meta = g_freshmeta[s];
    } else {
        q = make_ulonglong2(0ULL, 0ULL);
        meta = (1 << 16);
    }
}

// Resolve one row. All lanes redundantly maintain the consumed bitmask (same
// value/address stores), so no per-row __syncwarp is needed for visibility.
__device__ __forceinline__ bool rowp(int a, int lane, unsigned int* cons,
                                     ulonglong2 q, int meta, int& merges, int& stop) {
    bool ca = (cons[a >> 5] >> (a & 31)) & 1u;  // lane-uniform
    int partner = -1;
    if (!ca) {
        int L = meta & 0xFFFF;
        int comp = meta >> 16;
        unsigned long long e0 = (lane * 2 < L) ? q.x : 0ULL;
        unsigned long long e1 = (lane * 2 + 1 < L) ? q.y : 0ULL;
        unsigned long long chosen = 0ULL;
        if (e0 != 0ULL) {
            int b = (int)(0xFFFFFFFFu - (unsigned int)(e0 & 0xFFFFFFFFull));
            if (!((cons[b >> 5] >> (b & 31)) & 1u)) chosen = e0;
        }
        if (chosen == 0ULL && e1 != 0ULL) {
            int b = (int)(0xFFFFFFFFu - (unsigned int)(e1 & 0xFFFFFFFFull));
            if (!((cons[b >> 5] >> (b & 31)) & 1u)) chosen = e1;
        }
        unsigned ba = __ballot_sync(FULLMASK, chosen != 0ULL);
        if (ba) {
            unsigned long long kf = __shfl_sync(FULLMASK, chosen, __ffs(ba) - 1);
            float v = __uint_as_float((unsigned int)(kf >> 32));
            if (v >= THR)
                partner = (int)(0xFFFFFFFFu - (unsigned int)(kf & 0xFFFFFFFFull));
        } else if (!comp) {
            stop = a;  // stale list, rebuild next pass
            return false;
        }
    }
    if (partner >= 0) {
        ++merges;  // uniform across lanes
        cons[partner >> 5] |= (1u << (partner & 31));  // redundant store, all lanes
    }
    if (lane == 0) g_partner[a] = partner;
    return true;
}

// ---------------- single-warp frontier sweep over fresh lists (4-deep prefetch) ----------
__device__ void sweep_warp(int m, int F, unsigned int* cons /*shared*/) {
    int lane = threadIdx.x;  // warp 0 only
    int Wend = (F + W_SLOTS < m) ? (F + W_SLOTS) : m;
    int n = Wend - F;

    ulonglong2 q0, q1, q2, q3;
    int m0, m1, m2, m3;
    load_slotp(0, n, lane, q0, m0);
    load_slotp(1, n, lane, q1, m1);
    load_slotp(2, n, lane, q2, m2);
    load_slotp(3, n, lane, q3, m3);

    int merges = 0, stop = -1;
    int s = 0;
    while (s < n && stop < 0) {
        if (!rowp(F + s, lane, cons, q0, m0, merges, stop)) break;
        load_slotp(s + 4, n, lane, q0, m0);
        if (++s >= n) break;
        if (!rowp(F + s, lane, cons, q1, m1, merges, stop)) break;
        load_slotp(s + 4, n, lane, q1, m1);
        if (++s >= n) break;
        if (!rowp(F + s, lane, cons, q2, m2, merges, stop)) break;
        load_slotp(s + 4, n, lane, q2, m2);
        if (++s >= n) break;
        if (!rowp(F + s, lane, cons, q3, m3, merges, stop)) break;
        load_slotp(s + 4, n, lane, q3, m3);
        ++s;
    }

    int newF = (stop >= 0) ? stop : Wend;
    __syncwarp();
    for (int w = lane; w < N_MAX / 32; w += 32) g_consumed[w] = cons[w];
    if (lane == 0) {
        g_frontier = newF;
        g_merges += merges;
        if (newF == m) {
            int tm = g_merges;
            if (tm == 0 || (m - tm) <= 1) g_done = 1;
        }
    }
}

// ---------------- one pass: parallel fresh builds + (last block) sequential sweep ----------------
__global__ void __launch_bounds__(256) k_pass() {  // <<<W_SLOTS/8, 256>>>
    int m = *(volatile int*)&g_m;
    int F = *(volatile int*)&g_frontier;
    if (*(volatile int*)&g_done || F >= m) return;

    __shared__ unsigned int s_cons[N_MAX / 32];
    __shared__ int s_last;
    int tid = threadIdx.x;
    if (tid < N_MAX / 32) s_cons[tid] = g_consumed[tid];
    __syncthreads();

    int warp = tid >> 5;
    int slot = blockIdx.x * 8 + warp;
    build_fresh(F + slot, m, slot, s_cons);

    __threadfence();   // release this thread's list writes
    __syncthreads();
    if (tid == 0) s_last = (atomicAdd(&g_ticket, 1) == (int)gridDim.x - 1);
    __syncthreads();
    if (!s_last) return;

    __threadfence();   // acquire other blocks' list writes
    if (warp == 0) sweep_warp(m, F, s_cons);
    __syncthreads();
    if (tid == 0) g_ticket = 0;
}

// ---------------- exact finish net: block-rescan remaining rows (normally a no-op) ------------
__global__ void __launch_bounds__(1024, 1) k_finish() {  // <<<1,1024>>>
    int m = g_m;
    int F = g_frontier;
    if (g_done || F >= m) return;

    __shared__ unsigned int cons[N_MAX / 32];
    __shared__ unsigned long long partial[32];
    int tid = threadIdx.x, lane = tid & 31, wid = tid >> 5;
    if (tid < N_MAX / 32) cons[tid] = g_consumed[tid];
    __syncthreads();

    int merges = 0;  // maintained by thread 0 only
    for (int a = F; a < m; ++a) {
        bool ca = (cons[a >> 5] >> (a & 31)) & 1u;  // uniform
        unsigned long long best = 0ULL;
        if (!ca) {
            const float* row = g_sim + (size_t)a * N_MAX;
            for (int b = a + 1 + tid; b < m; b += 1024) {
                if (!((cons[b >> 5] >> (b & 31)) & 1u)) {
                    unsigned long long key =
                        ((unsigned long long)__float_as_uint(row[b]) << 32) |
                        (unsigned int)(0xFFFFFFFFu - (unsigned)b);
                    if (key > best) best = key;
                }
            }
        }
        best = warpmax_u64(best);
        if (lane == 0) partial[wid] = best;
        __syncthreads();
        if (wid == 0) {
            unsigned long long p = warpmax_u64(partial[lane]);
            if (lane == 0) {
                int partner = -1;
                if (!ca && p != 0ULL) {
                    float v = __uint_as_float((unsigned int)(p >> 32));
                    if (v >= THR)
                        partner = (int)(0xFFFFFFFFu - (unsigned int)(p & 0xFFFFFFFFull));
                }
                g_partner[a] = partner;
                if (partner >= 0) {
                    ++merges;
                    cons[partner >> 5] |= (1u << (partner & 31));
                }
            }
        }
        __syncthreads();
    }
    if (tid < N_MAX / 32) g_consumed[tid] = cons[tid];
    if (tid == 0) {
        g_frontier = m;
        g_merges += merges;
        int tm = g_merges;
        if (tm == 0 || (m - tm) <= 1) g_done = 1;
    }
}

// ---------------- apply merges: fuse initiator, zero+kill partner ----------------
__global__ void k_apply() {  // <<<N_MAX, 256>>>
    int a = blockIdx.x;
    int p = g_partner[a];
    if (p < 0) return;
    int gi = g_idx[a];
    int gj = g_idx[p];
    float4* vi = (float4*)(g_emb + (size_t)gi * D);
    float4* vj = (float4*)(g_emb + (size_t)gj * D);
    int t = threadIdx.x;
    float4 x = vi[t];
    float4 y = vj[t];
    x.x = fminf(x.x + y.x, 1.0f);
    x.y = fminf(x.y + y.y, 1.0f);
    x.z = fminf(x.z + y.z, 1.0f);
    x.w = fminf(x.w + y.w, 1.0f);
    vi[t] = x;
    vj[t] = make_float4(0.f, 0.f, 0.f, 0.f);
    if (t == 0) g_alive[gj] = 0;
}

// ---------------- write output: emb then alive (as float) ----------------
__global__ void k_output(float* __restrict__ out, int out_size) {
    int i = blockIdx.x * blockDim.x + threadIdx.x;
    int stride = gridDim.x * blockDim.x;
    for (int t = i; t < N_MAX * D; t += stride)
        if (t < out_size) out[t] = g_emb[t];
    for (int r = i; r < N_MAX; r += stride) {
        int o = N_MAX * D + r;
        if (o < out_size) out[o] = g_alive[r] ? 1.0f : 0.0f;
    }
}

extern "C" void kernel_launch(void* const* d_in, const int* in_sizes, int n_in,
                              void* d_out, int out_size) {
    const float* in = (const float*)d_in[0];
    static const int pass_budget[ROUNDS] = {10, 26, 15, 10};
    k_init<<<4096, 256>>>(in);
    for (int r = 0; r < ROUNDS; ++r) {
        k_compact<<<1, 1024>>>();
        k_gather<<<N_MAX, 256>>>();
        dim3 grid(32, 32);
        k_gemm<<<grid, 256>>>();
        for (int p = 0; p < pass_budget[r]; ++p)
            k_pass<<<W_SLOTS / 8, 256>>>();
        k_finish<<<1, 1024>>>();
        k_apply<<<N_MAX, 256>>>();
    }
    k_output<<<4096, 256>>>((float*)d_out, out_size);
}